// round 7
// baseline (speedup 1.0000x reference)
#include <cuda_runtime.h>
#include <cstdint>

#define Bdim 64
#define Sdim 512
#define Wdim 256
#define Ddim 768
#define Ndim 96          // 32 attrs * 3 classes
#define KC   32          // K chunk
#define MT   128         // M tile per CTA
#define NITER (Ddim / KC)   // 24
#define SA_STRIDE 36     // padded row stride (floats): bank = lane for frag loads

__device__ __forceinline__ uint32_t f2tf32(float f) {
    uint32_t r;
    asm("cvt.rna.tf32.f32 %0, %1;" : "=r"(r) : "f"(f));
    return r;
}

__device__ __forceinline__ void mma_tf32(float* c,
    uint32_t a0, uint32_t a1, uint32_t a2, uint32_t a3,
    uint32_t b0, uint32_t b1)
{
    asm volatile(
        "mma.sync.aligned.m16n8k8.row.col.f32.tf32.tf32.f32 "
        "{%0,%1,%2,%3}, {%4,%5,%6,%7}, {%8,%9}, {%0,%1,%2,%3};"
        : "+f"(c[0]), "+f"(c[1]), "+f"(c[2]), "+f"(c[3])
        : "r"(a0), "r"(a1), "r"(a2), "r"(a3), "r"(b0), "r"(b1));
}

__global__ __launch_bounds__(256, 1)
void ner_gather_gemm(const float* __restrict__ seq,
                     const int*   __restrict__ widx,
                     const float* __restrict__ wgt,
                     const float* __restrict__ bias,
                     float*       __restrict__ out)
{
    __shared__ float sA[MT * SA_STRIDE];      // 18 KB, tf32-rounded A tile
    __shared__ float sB[Ndim * SA_STRIDE];    // 13.5 KB, tf32-rounded W tile
    __shared__ int   sIdx[MT];
    __shared__ float sBias[Ndim];

    const int t      = threadIdx.x;
    const int m_base = blockIdx.x * MT;       // 128 consecutive (b,w) rows
    const int bidx   = m_base >> 8;           // b (W=256, MT=128 -> b fixed per CTA)
    const int w_base = m_base & 255;

    if (t < MT)   sIdx[t]  = widx[bidx * Wdim + w_base + t];
    if (t < Ndim) sBias[t] = bias[t];
    __syncthreads();

    // A staging: thread t loads row rA, 16-col half hA (2 threads per 32-col row)
    const int rA = t >> 1;
    const int hA = (t & 1) * 16;
    const float* aRow = seq + (size_t)(bidx * Sdim + sIdx[rA]) * Ddim + hA;

    float4 ra[4];   // 16 floats of A chunk
    float4 rb[3];   // 12 floats of W chunk (96*32/256 per thread)

    const int wid  = t >> 5;
    const int lane = t & 31;
    const int grp  = lane >> 2;   // 0..7
    const int kq   = lane & 3;    // 0..3
    const int rowA = wid * 16 + grp;

    float acc[12][4];
    #pragma unroll
    for (int i = 0; i < 12; i++) {
        acc[i][0] = 0.f; acc[i][1] = 0.f; acc[i][2] = 0.f; acc[i][3] = 0.f;
    }

    // ---- prefetch chunk 0 ----
    #pragma unroll
    for (int j = 0; j < 4; j++)
        ra[j] = *reinterpret_cast<const float4*>(aRow + 0 + 4 * j);
    #pragma unroll
    for (int j = 0; j < 3; j++) {
        int i = t + 256 * j;
        int n = i >> 3, c = (i & 7) * 4;
        rb[j] = *reinterpret_cast<const float4*>(wgt + n * Ddim + 0 + c);
    }
    // store chunk 0 to smem with RNA tf32 rounding
    #pragma unroll
    for (int j = 0; j < 4; j++) {
        uint4 u = { f2tf32(ra[j].x), f2tf32(ra[j].y), f2tf32(ra[j].z), f2tf32(ra[j].w) };
        *reinterpret_cast<uint4*>(&sA[rA * SA_STRIDE + hA + 4 * j]) = u;
    }
    #pragma unroll
    for (int j = 0; j < 3; j++) {
        int i = t + 256 * j;
        int n = i >> 3, c = (i & 7) * 4;
        uint4 u = { f2tf32(rb[j].x), f2tf32(rb[j].y), f2tf32(rb[j].z), f2tf32(rb[j].w) };
        *reinterpret_cast<uint4*>(&sB[n * SA_STRIDE + c]) = u;
    }
    __syncthreads();

    for (int it = 0; it < NITER; ++it) {
        // prefetch next chunk into registers (hidden under compute)
        if (it + 1 < NITER) {
            const int kc = (it + 1) * KC;
            #pragma unroll
            for (int j = 0; j < 4; j++)
                ra[j] = *reinterpret_cast<const float4*>(aRow + kc + 4 * j);
            #pragma unroll
            for (int j = 0; j < 3; j++) {
                int i = t + 256 * j;
                int n = i >> 3, c = (i & 7) * 4;
                rb[j] = *reinterpret_cast<const float4*>(wgt + n * Ddim + kc + c);
            }
        }

        // compute current chunk from smem
        #pragma unroll
        for (int k8 = 0; k8 < KC; k8 += 8) {
            uint32_t a0 = __float_as_uint(sA[ rowA      * SA_STRIDE + k8 + kq    ]);
            uint32_t a1 = __float_as_uint(sA[(rowA + 8) * SA_STRIDE + k8 + kq    ]);
            uint32_t a2 = __float_as_uint(sA[ rowA      * SA_STRIDE + k8 + kq + 4]);
            uint32_t a3 = __float_as_uint(sA[(rowA + 8) * SA_STRIDE + k8 + kq + 4]);
            #pragma unroll
            for (int nt = 0; nt < 12; ++nt) {
                int n = nt * 8 + grp;
                uint32_t b0 = __float_as_uint(sB[n * SA_STRIDE + k8 + kq    ]);
                uint32_t b1 = __float_as_uint(sB[n * SA_STRIDE + k8 + kq + 4]);
                mma_tf32(acc[nt], a0, a1, a2, a3, b0, b1);
            }
        }
        __syncthreads();

        if (it + 1 < NITER) {
            #pragma unroll
            for (int j = 0; j < 4; j++) {
                uint4 u = { f2tf32(ra[j].x), f2tf32(ra[j].y), f2tf32(ra[j].z), f2tf32(ra[j].w) };
                *reinterpret_cast<uint4*>(&sA[rA * SA_STRIDE + hA + 4 * j]) = u;
            }
            #pragma unroll
            for (int j = 0; j < 3; j++) {
                int i = t + 256 * j;
                int n = i >> 3, c = (i & 7) * 4;
                uint4 u = { f2tf32(rb[j].x), f2tf32(rb[j].y), f2tf32(rb[j].z), f2tf32(rb[j].w) };
                *reinterpret_cast<uint4*>(&sB[n * SA_STRIDE + c]) = u;
            }
            __syncthreads();
        }
    }

    // ---- epilogue: bias add + scattered store into [A, B, W, 3] layout ----
    #pragma unroll
    for (int nt = 0; nt < 12; ++nt) {
        #pragma unroll
        for (int e = 0; e < 4; ++e) {
            int n = nt * 8 + 2 * kq + (e & 1);           // column in [0,96)
            int m = m_base + rowA + (e >> 1) * 8;        // global row (b*W + w)
            float v = acc[nt][e] + sBias[n];
            int a = n / 3;
            int c = n - a * 3;
            out[(size_t)a * (Bdim * Wdim * 3) + (size_t)m * 3 + c] = v;
        }
    }
}

extern "C" void kernel_launch(void* const* d_in, const int* in_sizes, int n_in,
                              void* d_out, int out_size)
{
    const float* seq  = (const float*)d_in[0];   // [64, 512, 768] f32
    const int*   widx = (const int*)  d_in[1];   // [64, 256] i32
    const float* wgt  = (const float*)d_in[2];   // [32, 3, 768] f32
    const float* bias = (const float*)d_in[3];   // [32, 3] f32
    float* out = (float*)d_out;                  // [32, 64, 256, 3] f32

    ner_gather_gemm<<<(Bdim * Wdim) / MT, 256>>>(seq, widx, wgt, bias, out);
}